// round 13
// baseline (speedup 1.0000x reference)
#include <cuda_runtime.h>
#include <cuda_fp16.h>
#include <math.h>
#include <stdint.h>

// ---------------- Problem constants ----------------
#define BB      4
#define LL      2048
#define DM      1024
#define DI      2048
#define DC      4
#define MROWS   (BB * LL)          // 8192 token rows

// ---------------- Scratch (device globals; no cudaMalloc allowed) ----------
__device__ float g_left [(size_t)MROWS * DI];
__device__ float g_xl   [(size_t)MROWS * DI];
__device__ float g_delta[(size_t)MROWS * DI];
__device__ float g_gate [(size_t)MROWS * DI];
__device__ float g_y    [(size_t)MROWS * DI];
__device__ float g_BC   [(size_t)MROWS * 32];
// fp16 split planes.
__device__ __align__(16) __half g_x2  [(size_t)MROWS * 2 * DM];     // x, 2-term A
__device__ __align__(16) __half g_wlr2[(size_t)2 * DI * 2 * DM];    // [W_left; W_right], 2-term B
__device__ __align__(16) __half g_wd3 [(size_t)DI * 3 * DI];        // W_delta, 3-term B
__device__ __align__(16) __half g_wo2 [(size_t)DM * 2 * DI];        // W_out, 2-term B
__device__ __align__(16) __half g_xl3 [(size_t)MROWS * 3 * DI];     // xl 3-term A; later LN-out 2-term A

// ---------------- scalar helpers ----------------
__device__ __forceinline__ float siluf(float x) { return x / (1.0f + __expf(-x)); }
__device__ __forceinline__ float softplus_clip(float x) {
    float sp = (x > 20.0f) ? x : log1pf(__expf(x));
    return fminf(fmaxf(sp, 1e-4f), 10.0f);
}
__device__ __forceinline__ void h_split(float v, __half& hi, __half& lo) {
    hi = __float2half_rn(v);
    lo = __float2half_rn(v - __half2float(hi));
}

// ---------------- PTX helpers (portable sm_80-class only) --------------------
__device__ __forceinline__ uint32_t smem_u32(const void* p) {
    uint32_t a;
    asm("{ .reg .u64 t; cvta.to.shared.u64 t, %1; cvt.u32.u64 %0, t; }" : "=r"(a) : "l"(p));
    return a;
}
__device__ __forceinline__ void cp_async16(uint32_t dst, const void* src) {
    asm volatile("cp.async.cg.shared.global [%0], [%1], 16;" :: "r"(dst), "l"(src) : "memory");
}
__device__ __forceinline__ void cp_commit() {
    asm volatile("cp.async.commit_group;" ::: "memory");
}
template <int N>
__device__ __forceinline__ void cp_wait_group() {
    asm volatile("cp.async.wait_group %0;" :: "n"(N) : "memory");
}
__device__ __forceinline__ void ldmx4(uint32_t& r0, uint32_t& r1, uint32_t& r2, uint32_t& r3,
                                      uint32_t addr) {
    asm volatile("ldmatrix.sync.aligned.m8n8.x4.shared.b16 {%0,%1,%2,%3}, [%4];"
                 : "=r"(r0), "=r"(r1), "=r"(r2), "=r"(r3) : "r"(addr));
}
__device__ __forceinline__ void mma16816(float* d, const uint32_t* a,
                                         uint32_t b0, uint32_t b1) {
    asm volatile(
        "mma.sync.aligned.m16n8k16.row.col.f32.f16.f16.f32 "
        "{%0,%1,%2,%3}, {%4,%5,%6,%7}, {%8,%9}, {%0,%1,%2,%3};"
        : "+f"(d[0]), "+f"(d[1]), "+f"(d[2]), "+f"(d[3])
        : "r"(a[0]), "r"(a[1]), "r"(a[2]), "r"(a[3]), "r"(b0), "r"(b1));
}

// ---------------- fp16 GEMM (BN=128):  C[M,N] = A[M,Kp] @ W[N,Kp]^T --------
#define EPI_NONE 0
#define EPI_SILU 1
#define EPI_SP   2
#define EPI_DUAL 3

#define HG_STAGES 3
#define HG_STG    32768                 // 16KB A + 16KB B per stage
#define HG_SMEM   (HG_STAGES * HG_STG)  // 96KB

template <int EPI>
__global__ __launch_bounds__(256, 2)
void hgemm_kernel(const __half* __restrict__ A, const __half* __restrict__ W,
                  const float* __restrict__ bias, float* __restrict__ C,
                  float* __restrict__ C2,
                  int M, int N, int K3)
{
    extern __shared__ char smem[];
    const uint32_t sbase = smem_u32(smem);

    const int tid  = threadIdx.x;
    const int lane = tid & 31;
    const int wid  = tid >> 5;
    const int wm   = wid & 3;           // 0..3
    const int wn   = wid >> 2;          // 0..1
    const int bm   = blockIdx.y * 128;
    const int bn   = blockIdx.x * 128;
    const int nch  = K3 >> 6;

    const int lr  = tid >> 1;
    const int lc0 = (tid & 1) * 4;
    const __half* gA = A + (size_t)(bm + lr) * K3 + lc0 * 8;
    const __half* gW = W + (size_t)(bn + lr) * K3 + lc0 * 8;
    uint32_t soff[4];
#pragma unroll
    for (int j = 0; j < 4; j++)
        soff[j] = (uint32_t)(lr * 128 + (((lc0 + j) ^ (lr & 7)) << 4));

    float acc[2][8][4];
#pragma unroll
    for (int i = 0; i < 2; i++)
#pragma unroll
        for (int n = 0; n < 8; n++)
#pragma unroll
            for (int q = 0; q < 4; q++) acc[i][n][q] = 0.0f;

    const int alr = lane & 15;
    const int ac8 = lane >> 4;

#pragma unroll
    for (int s = 0; s < HG_STAGES - 1; s++) {
        if (s < nch) {
            uint32_t sa = sbase + s * HG_STG;
            const __half* ga = gA + (size_t)s * 64;
            const __half* gw = gW + (size_t)s * 64;
#pragma unroll
            for (int j = 0; j < 4; j++) {
                cp_async16(sa + soff[j], ga + j * 8);
                cp_async16(sa + 16384 + soff[j], gw + j * 8);
            }
            cp_commit();
        }
    }

    for (int c = 0; c < nch; c++) {
        cp_wait_group<HG_STAGES - 2>();
        __syncthreads();

        int nc = c + HG_STAGES - 1;
        if (nc < nch) {
            uint32_t sa = sbase + (nc % HG_STAGES) * HG_STG;
            const __half* ga = gA + (size_t)nc * 64;
            const __half* gw = gW + (size_t)nc * 64;
#pragma unroll
            for (int j = 0; j < 4; j++) {
                cp_async16(sa + soff[j], ga + j * 8);
                cp_async16(sa + 16384 + soff[j], gw + j * 8);
            }
            cp_commit();
        }

        const uint32_t sa = sbase + (c % HG_STAGES) * HG_STG;
        const uint32_t sb = sa + 16384;
#pragma unroll
        for (int kk = 0; kk < 4; kk++) {
            const int c8 = kk * 2 + ac8;
            uint32_t a[2][4];
#pragma unroll
            for (int i = 0; i < 2; i++) {
                int row = wm * 32 + i * 16 + alr;
                ldmx4(a[i][0], a[i][1], a[i][2], a[i][3],
                      sa + row * 128 + ((c8 ^ (row & 7)) << 4));
            }
            uint32_t b[8][2];
#pragma unroll
            for (int j = 0; j < 4; j++) {
                int row = wn * 64 + j * 16 + alr;
                uint32_t r0, r1, r2, r3;
                ldmx4(r0, r1, r2, r3, sb + row * 128 + ((c8 ^ (row & 7)) << 4));
                b[2 * j][0] = r0; b[2 * j + 1][0] = r1;
                b[2 * j][1] = r2; b[2 * j + 1][1] = r3;
            }
#pragma unroll
            for (int i = 0; i < 2; i++)
#pragma unroll
                for (int n = 0; n < 8; n++)
                    mma16816(acc[i][n], a[i], b[n][0], b[n][1]);
        }
    }

    // ---------------- epilogue ----------------
    const int Nh = (EPI == EPI_DUAL) ? (N >> 1) : N;
    const bool second = (EPI == EPI_DUAL) && (bn >= Nh);
    float* dst = (EPI == EPI_DUAL) ? (second ? C2 : C) : C;
    const int cbase = second ? (bn - Nh) : bn;

#pragma unroll
    for (int i = 0; i < 2; i++) {
        int row = bm + wm * 32 + i * 16 + (lane >> 2);
#pragma unroll
        for (int n = 0; n < 8; n++) {
            int col = cbase + wn * 64 + n * 8 + (lane & 3) * 2;
            float v0 = acc[i][n][0], v1 = acc[i][n][1];
            float v2 = acc[i][n][2], v3 = acc[i][n][3];
            if (EPI == EPI_SILU || (EPI == EPI_DUAL && second)) {
                v0 = siluf(v0); v1 = siluf(v1); v2 = siluf(v2); v3 = siluf(v3);
            } else if (EPI == EPI_SP) {
                float b0 = bias[col], b1 = bias[col + 1];
                v0 = softplus_clip(v0 + b0); v1 = softplus_clip(v1 + b1);
                v2 = softplus_clip(v2 + b0); v3 = softplus_clip(v3 + b1);
            }
            *(float2*)&dst[(size_t)row * Nh + col]       = make_float2(v0, v1);
            *(float2*)&dst[(size_t)(row + 8) * Nh + col] = make_float2(v2, v3);
        }
    }
}

// ---------------- fp16 split expansion prepasses ------------------------------
template <int PAT>
__global__ __launch_bounds__(256)
void expand3_kernel(const float* __restrict__ in, __half* __restrict__ out,
                    int K, size_t total4)
{
    size_t i4 = (size_t)blockIdx.x * blockDim.x + threadIdx.x;
    if (i4 >= total4) return;
    size_t i = i4 * 4;
    float4 v = *(const float4*)(in + i);
    __half h[4], l[4];
    h_split(v.x, h[0], l[0]); h_split(v.y, h[1], l[1]);
    h_split(v.z, h[2], l[2]); h_split(v.w, h[3], l[3]);
    size_t r = i / K;
    int    k = (int)(i - r * K);
    __half* orow = out + r * (size_t)(3 * K);
    uint2 hp = *(uint2*)h, lp = *(uint2*)l;
    if (PAT == 0) {
        *(uint2*)(orow + k) = hp; *(uint2*)(orow + K + k) = hp; *(uint2*)(orow + 2 * K + k) = lp;
    } else {
        *(uint2*)(orow + k) = hp; *(uint2*)(orow + K + k) = lp; *(uint2*)(orow + 2 * K + k) = hp;
    }
}

template <int PAT>
__global__ __launch_bounds__(256)
void expand2_kernel(const float* __restrict__ in, __half* __restrict__ out,
                    int K, size_t total4)
{
    size_t i4 = (size_t)blockIdx.x * blockDim.x + threadIdx.x;
    if (i4 >= total4) return;
    size_t i = i4 * 4;
    float4 v = *(const float4*)(in + i);
    __half h[4], l[4];
    h_split(v.x, h[0], l[0]); h_split(v.y, h[1], l[1]);
    h_split(v.z, h[2], l[2]); h_split(v.w, h[3], l[3]);
    size_t r = i / K;
    int    k = (int)(i - r * K);
    __half* orow = out + r * (size_t)(2 * K);
    uint2 hp = *(uint2*)h, lp = *(uint2*)l;
    *(uint2*)(orow + k) = hp;
    if (PAT == 0) *(uint2*)(orow + K + k) = lp;
    else          *(uint2*)(orow + K + k) = hp;
}

__global__ __launch_bounds__(256)
void expand2_dual_kernel(const float* __restrict__ in1, const float* __restrict__ in2,
                         __half* __restrict__ out, int K, size_t half4)
{
    size_t i4 = (size_t)blockIdx.x * blockDim.x + threadIdx.x;
    if (i4 >= 2 * half4) return;
    const bool lo2 = (i4 >= half4);
    size_t j = (lo2 ? (i4 - half4) : i4) * 4;
    float4 v = *(const float4*)((lo2 ? in2 : in1) + j);
    __half h[4], l[4];
    h_split(v.x, h[0], l[0]); h_split(v.y, h[1], l[1]);
    h_split(v.z, h[2], l[2]); h_split(v.w, h[3], l[3]);
    size_t r = j / K + (lo2 ? DI : 0);
    int    k = (int)(j % K);
    __half* orow = out + r * (size_t)(2 * K);
    uint2 hp = *(uint2*)h;
    *(uint2*)(orow + k) = hp;
    *(uint2*)(orow + K + k) = hp;
}

// ---------------- small GEMM for B/C projections: N=32 ----------------------
__global__ __launch_bounds__(256)
void sgemm_bc_kernel(const float* __restrict__ A, const float* __restrict__ WB,
                     const float* __restrict__ WC, float* __restrict__ C,
                     int M, int K)
{
    const int BM = 64, BK = 8;
    __shared__ __align__(16) float As[BK][BM];
    __shared__ __align__(16) float Ws[BK][32];

    const int tid = threadIdx.x;
    const int bm  = blockIdx.x * BM;
    const int tx  = tid & 31;
    const int ty  = tid >> 5;

    const bool la = (tid < 128);
    const int  ar = tid >> 1, ac = (tid & 1) * 4;
    const bool lw = (tid >= 128 && tid < 192);
    const int  wt = tid - 128, wr = wt >> 1, wc = (wt & 1) * 4;

    const float* Ap = A + (size_t)(bm + ar) * K + ac;
    const float* Wp = (wr < 16 ? WB + (size_t)wr * K : WC + (size_t)(wr - 16) * K) + wc;

    float acc[8];
#pragma unroll
    for (int i = 0; i < 8; i++) acc[i] = 0.0f;

    float4 aR = la ? *(const float4*)Ap : make_float4(0, 0, 0, 0);
    float4 wR = lw ? *(const float4*)Wp : make_float4(0, 0, 0, 0);

    const int nsteps = K / BK;
    for (int s = 0; s < nsteps; s++) {
        if (la) {
            As[ac + 0][ar] = aR.x; As[ac + 1][ar] = aR.y;
            As[ac + 2][ar] = aR.z; As[ac + 3][ar] = aR.w;
        }
        if (lw) {
            Ws[wc + 0][wr] = wR.x; Ws[wc + 1][wr] = wR.y;
            Ws[wc + 2][wr] = wR.z; Ws[wc + 3][wr] = wR.w;
        }
        __syncthreads();
        if (s + 1 < nsteps) {
            if (la) aR = *(const float4*)(Ap + (size_t)(s + 1) * BK);
            if (lw) wR = *(const float4*)(Wp + (size_t)(s + 1) * BK);
        }
#pragma unroll
        for (int k = 0; k < BK; k++) {
            float wf = Ws[k][tx];
            float4 a0 = *(const float4*)&As[k][ty * 8];
            float4 a1 = *(const float4*)&As[k][ty * 8 + 4];
            acc[0] = fmaf(a0.x, wf, acc[0]);
            acc[1] = fmaf(a0.y, wf, acc[1]);
            acc[2] = fmaf(a0.z, wf, acc[2]);
            acc[3] = fmaf(a0.w, wf, acc[3]);
            acc[4] = fmaf(a1.x, wf, acc[4]);
            acc[5] = fmaf(a1.y, wf, acc[5]);
            acc[6] = fmaf(a1.z, wf, acc[6]);
            acc[7] = fmaf(a1.w, wf, acc[7]);
        }
        __syncthreads();
    }
#pragma unroll
    for (int i = 0; i < 8; i++)
        C[(size_t)(bm + ty * 8 + i) * 32 + tx] = acc[i];
}

// ---------------- causal depthwise conv + silu + fp16 3-term split ----------
__global__ __launch_bounds__(256)
void conv_silu_split_kernel(const float* __restrict__ left,
                            const float* __restrict__ cw,
                            const float* __restrict__ cb,
                            float* __restrict__ xl,
                            __half* __restrict__ xl3)
{
    size_t t = (size_t)blockIdx.x * blockDim.x + threadIdx.x;
    if (t >= (size_t)MROWS * DI / 4) return;
    int d = (int)((t * 4) % DI);
    size_t row = (t * 4) / DI;
    int l = (int)(row % LL);

    const float4 cbv = *(const float4*)&cb[d];
    float acc[4] = {cbv.x, cbv.y, cbv.z, cbv.w};
    float4 w0 = *(const float4*)&cw[(size_t)d * DC];
    float4 w1 = *(const float4*)&cw[(size_t)(d + 1) * DC];
    float4 w2 = *(const float4*)&cw[(size_t)(d + 2) * DC];
    float4 w3 = *(const float4*)&cw[(size_t)(d + 3) * DC];
    const float* wv[4] = {&w0.x, &w1.x, &w2.x, &w3.x};

#pragma unroll
    for (int j = 0; j < DC; j++) {
        int ls = l + j - (DC - 1);
        if (ls >= 0) {
            const float4 v = *(const float4*)&left[(row + (size_t)(j - (DC - 1))) * DI + d];
#pragma unroll
            for (int q = 0; q < 4; q++)
                acc[q] = fmaf(wv[q][j], (&v.x)[q], acc[q]);
        }
    }
    __half h[4], lo[4];
    float o[4];
#pragma unroll
    for (int q = 0; q < 4; q++) {
        o[q] = siluf(acc[q]);
        h_split(o[q], h[q], lo[q]);
    }
    *(float4*)&xl[row * DI + d] = make_float4(o[0], o[1], o[2], o[3]);
    __half* orow = xl3 + row * (size_t)(3 * DI);
    *(uint2*)(orow + d) = *(uint2*)h;
    *(uint2*)(orow + DI + d) = *(uint2*)h;
    *(uint2*)(orow + 2 * DI + d) = *(uint2*)lo;
}

// ---------------- selective scan: 8 threads per (b,d) channel, MLP=4 --------
__global__ __launch_bounds__(256)
void scan_kernel(const float* __restrict__ delta, const float* __restrict__ xl,
                 const float* __restrict__ BC, const float* __restrict__ A_log,
                 float* __restrict__ y)
{
    int g   = blockIdx.x * blockDim.x + threadIdx.x;
    int grp = g & 7;
    int ch  = g >> 3;
    int d   = ch % DI;
    int b   = ch / DI;

    float Av0, Av1;
    Av0 = -log1pf(expf(A_log[grp * 2 + 0]));
    Av1 = -log1pf(expf(A_log[grp * 2 + 1]));

    float h0 = 0.f, h1 = 0.f;
    size_t rb = (size_t)b * LL;

    const float* dp = delta + rb * DI + d;
    const float* xp = xl    + rb * DI + d;
    const float* bp = BC + rb * 32 + grp * 2;
    float*       yp = y  + rb * DI + d;

    float  dtb[4], xtb[4];
    float2 Bb[4], Cb[4];
#pragma unroll
    for (int i = 0; i < 4; i++) {
        dtb[i] = dp[(size_t)i * DI];
        xtb[i] = xp[(size_t)i * DI];
        Bb[i]  = *(const float2*)(bp + (size_t)i * 32);
        Cb[i]  = *(const float2*)(bp + (size_t)i * 32 + 16);
    }

#pragma unroll 4
    for (int l = 0; l < LL; l++) {
        const int s = l & 3;
        float  dt = dtb[s], xt = xtb[s];
        float2 Bv = Bb[s],  Cv = Cb[s];

        if (l + 4 < LL) {
            dtb[s] = dp[(size_t)(l + 4) * DI];
            xtb[s] = xp[(size_t)(l + 4) * DI];
            Bb[s]  = *(const float2*)(bp + (size_t)(l + 4) * 32);
            Cb[s]  = *(const float2*)(bp + (size_t)(l + 4) * 32 + 16);
        }

        float w  = dt * xt;
        float a0 = __expf(dt * Av0);
        float a1 = __expf(dt * Av1);
        h0 = fmaf(a0, h0, w * Bv.x);
        h1 = fmaf(a1, h1, w * Bv.y);
        float p = h0 * Cv.x + h1 * Cv.y;
        p += __shfl_xor_sync(0xffffffffu, p, 1);
        p += __shfl_xor_sync(0xffffffffu, p, 2);
        p += __shfl_xor_sync(0xffffffffu, p, 4);
        if (grp == 0) yp[(size_t)l * DI] = p;
    }
}

// ---------------- gated layernorm -> fp16 2-term A planes -------------------
__global__ __launch_bounds__(256)
void ln_gate_split_kernel(const float* __restrict__ y, const float* __restrict__ gate,
                          const float* __restrict__ lng, const float* __restrict__ lnb,
                          __half* __restrict__ out2)
{
    int row = blockIdx.x;
    int tid = threadIdx.x;
    const float* yr = y    + (size_t)row * DI;
    const float* gr = gate + (size_t)row * DI;

    float v[8];
    float s = 0.f, sq = 0.f;
#pragma unroll
    for (int i = 0; i < 8; i++) {
        int c = tid + i * 256;
        v[i] = yr[c] * gr[c];
        s  += v[i];
        sq += v[i] * v[i];
    }
    __shared__ float rs[8], rq[8];
#pragma unroll
    for (int o = 16; o > 0; o >>= 1) {
        s  += __shfl_xor_sync(0xffffffffu, s,  o);
        sq += __shfl_xor_sync(0xffffffffu, sq, o);
    }
    if ((tid & 31) == 0) { rs[tid >> 5] = s; rq[tid >> 5] = sq; }
    __syncthreads();
    float ts = 0.f, tq = 0.f;
#pragma unroll
    for (int w = 0; w < 8; w++) { ts += rs[w]; tq += rq[w]; }

    float mu  = ts * (1.0f / DI);
    float var = tq * (1.0f / DI) - mu * mu;
    float inv = rsqrtf(var + 1e-5f);

    __half* orow = out2 + (size_t)row * (2 * DI);
#pragma unroll
    for (int i = 0; i < 8; i++) {
        int c = tid + i * 256;
        float o = (v[i] - mu) * inv * lng[c] + lnb[c];
        __half hi, lo;
        h_split(o, hi, lo);
        orow[c] = hi; orow[DI + c] = lo;
    }
}

// ---------------- side stream + events (static init; no device memory) ------
static cudaStream_t g_side = nullptr;
static cudaEvent_t  g_ev_fork = nullptr, g_ev_w = nullptr,
                    g_ev_conv = nullptr, g_ev_bc = nullptr;
static struct SideInit {
    SideInit() {
        cudaStreamCreateWithFlags(&g_side, cudaStreamNonBlocking);
        cudaEventCreateWithFlags(&g_ev_fork, cudaEventDisableTiming);
        cudaEventCreateWithFlags(&g_ev_w,    cudaEventDisableTiming);
        cudaEventCreateWithFlags(&g_ev_conv, cudaEventDisableTiming);
        cudaEventCreateWithFlags(&g_ev_bc,   cudaEventDisableTiming);
    }
} g_side_init;

// ---------------- launch --------------------------------------------------
extern "C" void kernel_launch(void* const* d_in, const int* in_sizes, int n_in,
                              void* d_out, int out_size)
{
    const float* x       = (const float*)d_in[0];
    const float* W_left  = (const float*)d_in[1];
    const float* conv_w  = (const float*)d_in[2];
    const float* conv_b  = (const float*)d_in[3];
    const float* W_delta = (const float*)d_in[4];
    const float* b_delta = (const float*)d_in[5];
    const float* W_B     = (const float*)d_in[6];
    const float* W_C     = (const float*)d_in[7];
    const float* A_log   = (const float*)d_in[8];
    const float* W_right = (const float*)d_in[9];
    const float* ln_g    = (const float*)d_in[10];
    const float* ln_b    = (const float*)d_in[11];
    const float* W_out   = (const float*)d_in[12];
    float*       out     = (float*)d_out;

    float *left, *xl, *delta, *gate, *y, *BC;
    __half *x2, *wlr2, *wd3, *wo2, *xl3;
    cudaGetSymbolAddress((void**)&left,  g_left);
    cudaGetSymbolAddress((void**)&xl,    g_xl);
    cudaGetSymbolAddress((void**)&delta, g_delta);
    cudaGetSymbolAddress((void**)&gate,  g_gate);
    cudaGetSymbolAddress((void**)&y,     g_y);
    cudaGetSymbolAddress((void**)&BC,    g_BC);
    cudaGetSymbolAddress((void**)&x2,    g_x2);
    cudaGetSymbolAddress((void**)&wlr2,  g_wlr2);
    cudaGetSymbolAddress((void**)&wd3,   g_wd3);
    cudaGetSymbolAddress((void**)&wo2,   g_wo2);
    cudaGetSymbolAddress((void**)&xl3,   g_xl3);

    cudaFuncSetAttribute(hgemm_kernel<EPI_NONE>, cudaFuncAttributeMaxDynamicSharedMemorySize, HG_SMEM);
    cudaFuncSetAttribute(hgemm_kernel<EPI_DUAL>, cudaFuncAttributeMaxDynamicSharedMemorySize, HG_SMEM);
    cudaFuncSetAttribute(hgemm_kernel<EPI_SP>,   cudaFuncAttributeMaxDynamicSharedMemorySize, HG_SMEM);

    const cudaStream_t s0 = 0;           // legacy default stream (captured)
    size_t n4;

    // ---- fork side branch: weight expansions (no deps on main chain) ----
    cudaEventRecord(g_ev_fork, s0);
    cudaStreamWaitEvent(g_side, g_ev_fork, 0);

    // side: W_delta 3-term expansion + W_out 2-term expansion
    n4 = (size_t)DI * DI / 4;
    expand3_kernel<1><<<(int)((n4 + 255) / 256), 256, 0, g_side>>>(W_delta, wd3, DI, n4);
    n4 = (size_t)DM * DI / 4;
    expand2_kernel<1><<<(int)((n4 + 255) / 256), 256, 0, g_side>>>(W_out, wo2, DI, n4);
    cudaEventRecord(g_ev_w, g_side);

    // main: x 2-term expansion
    n4 = (size_t)MROWS * DM / 4;
    expand2_kernel<0><<<(int)((n4 + 255) / 256), 256, 0, s0>>>(x, x2, DM, n4);

    // main: merged [W_left; W_right] 2-term expansion
    n4 = (size_t)DI * DM / 4;
    expand2_dual_kernel<<<(int)((2 * n4 + 255) / 256), 256, 0, s0>>>(W_left, W_right, wlr2, DM, n4);

    // main: merged [left | gate] = x @ [W_left;W_right]^T
    hgemm_kernel<EPI_DUAL><<<dim3(2 * DI / 128, MROWS / 128), 256, HG_SMEM, s0>>>(
        x2, wlr2, nullptr, left, gate, MROWS, 2 * DI, 2 * DM);

    // main: conv + silu + 3-term split
    conv_silu_split_kernel<<<(int)(((size_t)MROWS * DI / 4 + 255) / 256), 256, 0, s0>>>(
        left, conv_w, conv_b, xl, xl3);
    cudaEventRecord(g_ev_conv, s0);

    // side: BC projection depends only on xl (conv) -> overlaps delta GEMM
    cudaStreamWaitEvent(g_side, g_ev_conv, 0);
    sgemm_bc_kernel<<<MROWS / 64, 256, 0, g_side>>>(xl, W_B, W_C, BC, MROWS, DI);
    cudaEventRecord(g_ev_bc, g_side);

    // main: delta GEMM needs wd3 (side) + xl3 (main)
    cudaStreamWaitEvent(s0, g_ev_w, 0);
    hgemm_kernel<EPI_SP><<<dim3(DI / 128, MROWS / 128), 256, HG_SMEM, s0>>>(
        xl3, wd3, b_delta, delta, nullptr, MROWS, DI, 3 * DI);

    // main: scan needs delta (main) + BC (side)
    cudaStreamWaitEvent(s0, g_ev_bc, 0);
    scan_kernel<<<(BB * DI * 8) / 256, 256, 0, s0>>>(delta, xl, BC, A_log, y);

    // main: LN(y*gate) -> 2-term A planes
    ln_gate_split_kernel<<<MROWS, 256, 0, s0>>>(y, gate, ln_g, ln_b, xl3);

    // main: out = ln_out @ W_out^T  (wo2 ready via g_ev_w wait above)
    hgemm_kernel<EPI_NONE><<<dim3(DM / 128, MROWS / 128), 256, HG_SMEM, s0>>>(
        xl3, wo2, nullptr, out, nullptr, MROWS, DM, 2 * DI);
}

// round 14
// speedup vs baseline: 1.0378x; 1.0378x over previous
#include <cuda_runtime.h>
#include <cuda_fp16.h>
#include <math.h>
#include <stdint.h>

// ---------------- Problem constants ----------------
#define BB      4
#define LL      2048
#define DM      1024
#define DI      2048
#define DC      4
#define MROWS   (BB * LL)          // 8192 token rows

// ---------------- Scratch (device globals; no cudaMalloc allowed) ----------
__device__ float g_left [(size_t)MROWS * DI];
__device__ float g_xl   [(size_t)MROWS * DI];
__device__ float g_delta[(size_t)MROWS * DI];
__device__ float g_gate [(size_t)MROWS * DI];
__device__ float g_y    [(size_t)MROWS * DI];
__device__ float g_BC   [(size_t)MROWS * 32];
// fp16 split planes.
// 2-term: A pattern = [hi|lo], B pattern = [hi|hi]   (C = A_exact x Bhi)
// 3-term: A pattern = [hi|hi|lo], B pattern = [hi|lo|hi]
__device__ __align__(16) __half g_x2  [(size_t)MROWS * 2 * DM];     // x, 2-term A
__device__ __align__(16) __half g_wlr2[(size_t)2 * DI * 2 * DM];    // [W_left; W_right], 2-term B
__device__ __align__(16) __half g_wd3 [(size_t)DI * 3 * DI];        // W_delta, 3-term B
__device__ __align__(16) __half g_wo2 [(size_t)DM * 2 * DI];        // W_out, 2-term B
__device__ __align__(16) __half g_xl3 [(size_t)MROWS * 3 * DI];     // xl 3-term A; later LN-out 2-term A

// ---------------- scalar helpers ----------------
__device__ __forceinline__ float siluf(float x) { return x / (1.0f + __expf(-x)); }
__device__ __forceinline__ float softplus_clip(float x) {
    float sp = (x > 20.0f) ? x : log1pf(__expf(x));
    return fminf(fmaxf(sp, 1e-4f), 10.0f);
}
__device__ __forceinline__ void h_split(float v, __half& hi, __half& lo) {
    hi = __float2half_rn(v);
    lo = __float2half_rn(v - __half2float(hi));
}

// ---------------- PTX helpers (portable sm_80-class only) --------------------
__device__ __forceinline__ uint32_t smem_u32(const void* p) {
    uint32_t a;
    asm("{ .reg .u64 t; cvta.to.shared.u64 t, %1; cvt.u32.u64 %0, t; }" : "=r"(a) : "l"(p));
    return a;
}
__device__ __forceinline__ void cp_async16(uint32_t dst, const void* src) {
    asm volatile("cp.async.cg.shared.global [%0], [%1], 16;" :: "r"(dst), "l"(src) : "memory");
}
__device__ __forceinline__ void cp_commit() {
    asm volatile("cp.async.commit_group;" ::: "memory");
}
template <int N>
__device__ __forceinline__ void cp_wait_group() {
    asm volatile("cp.async.wait_group %0;" :: "n"(N) : "memory");
}
__device__ __forceinline__ void ldmx4(uint32_t& r0, uint32_t& r1, uint32_t& r2, uint32_t& r3,
                                      uint32_t addr) {
    asm volatile("ldmatrix.sync.aligned.m8n8.x4.shared.b16 {%0,%1,%2,%3}, [%4];"
                 : "=r"(r0), "=r"(r1), "=r"(r2), "=r"(r3) : "r"(addr));
}
__device__ __forceinline__ void mma16816(float* d, const uint32_t* a,
                                         uint32_t b0, uint32_t b1) {
    asm volatile(
        "mma.sync.aligned.m16n8k16.row.col.f32.f16.f16.f32 "
        "{%0,%1,%2,%3}, {%4,%5,%6,%7}, {%8,%9}, {%0,%1,%2,%3};"
        : "+f"(d[0]), "+f"(d[1]), "+f"(d[2]), "+f"(d[3])
        : "r"(a[0]), "r"(a[1]), "r"(a[2]), "r"(a[3]), "r"(b0), "r"(b1));
}

// ---------------- fp16 GEMM (BN=128):  C[M,N] = A[M,Kp] @ W[N,Kp]^T --------
#define EPI_NONE 0
#define EPI_SILU 1
#define EPI_SP   2
#define EPI_DUAL 3

#define HG_STAGES 3
#define HG_STG    32768                 // 16KB A + 16KB B per stage
#define HG_SMEM   (HG_STAGES * HG_STG)  // 96KB

template <int EPI>
__global__ __launch_bounds__(256, 2)
void hgemm_kernel(const __half* __restrict__ A, const __half* __restrict__ W,
                  const float* __restrict__ bias, float* __restrict__ C,
                  float* __restrict__ C2,
                  int M, int N, int K3)
{
    extern __shared__ char smem[];
    const uint32_t sbase = smem_u32(smem);

    const int tid  = threadIdx.x;
    const int lane = tid & 31;
    const int wid  = tid >> 5;
    const int wm   = wid & 3;           // 0..3
    const int wn   = wid >> 2;          // 0..1
    const int bm   = blockIdx.y * 128;
    const int bn   = blockIdx.x * 128;
    const int nch  = K3 >> 6;

    const int lr  = tid >> 1;
    const int lc0 = (tid & 1) * 4;
    const __half* gA = A + (size_t)(bm + lr) * K3 + lc0 * 8;
    const __half* gW = W + (size_t)(bn + lr) * K3 + lc0 * 8;
    uint32_t soff[4];
#pragma unroll
    for (int j = 0; j < 4; j++)
        soff[j] = (uint32_t)(lr * 128 + (((lc0 + j) ^ (lr & 7)) << 4));

    float acc[2][8][4];
#pragma unroll
    for (int i = 0; i < 2; i++)
#pragma unroll
        for (int n = 0; n < 8; n++)
#pragma unroll
            for (int q = 0; q < 4; q++) acc[i][n][q] = 0.0f;

    const int alr = lane & 15;
    const int ac8 = lane >> 4;

#pragma unroll
    for (int s = 0; s < HG_STAGES - 1; s++) {
        if (s < nch) {
            uint32_t sa = sbase + s * HG_STG;
            const __half* ga = gA + (size_t)s * 64;
            const __half* gw = gW + (size_t)s * 64;
#pragma unroll
            for (int j = 0; j < 4; j++) {
                cp_async16(sa + soff[j], ga + j * 8);
                cp_async16(sa + 16384 + soff[j], gw + j * 8);
            }
            cp_commit();
        }
    }

    for (int c = 0; c < nch; c++) {
        cp_wait_group<HG_STAGES - 2>();
        __syncthreads();

        int nc = c + HG_STAGES - 1;
        if (nc < nch) {
            uint32_t sa = sbase + (nc % HG_STAGES) * HG_STG;
            const __half* ga = gA + (size_t)nc * 64;
            const __half* gw = gW + (size_t)nc * 64;
#pragma unroll
            for (int j = 0; j < 4; j++) {
                cp_async16(sa + soff[j], ga + j * 8);
                cp_async16(sa + 16384 + soff[j], gw + j * 8);
            }
            cp_commit();
        }

        const uint32_t sa = sbase + (c % HG_STAGES) * HG_STG;
        const uint32_t sb = sa + 16384;
#pragma unroll
        for (int kk = 0; kk < 4; kk++) {
            const int c8 = kk * 2 + ac8;
            uint32_t a[2][4];
#pragma unroll
            for (int i = 0; i < 2; i++) {
                int row = wm * 32 + i * 16 + alr;
                ldmx4(a[i][0], a[i][1], a[i][2], a[i][3],
                      sa + row * 128 + ((c8 ^ (row & 7)) << 4));
            }
            uint32_t b[8][2];
#pragma unroll
            for (int j = 0; j < 4; j++) {
                int row = wn * 64 + j * 16 + alr;
                uint32_t r0, r1, r2, r3;
                ldmx4(r0, r1, r2, r3, sb + row * 128 + ((c8 ^ (row & 7)) << 4));
                b[2 * j][0] = r0; b[2 * j + 1][0] = r1;
                b[2 * j][1] = r2; b[2 * j + 1][1] = r3;
            }
#pragma unroll
            for (int i = 0; i < 2; i++)
#pragma unroll
                for (int n = 0; n < 8; n++)
                    mma16816(acc[i][n], a[i], b[n][0], b[n][1]);
        }
    }

    // ---------------- epilogue ----------------
    const int Nh = (EPI == EPI_DUAL) ? (N >> 1) : N;
    const bool second = (EPI == EPI_DUAL) && (bn >= Nh);
    float* dst = (EPI == EPI_DUAL) ? (second ? C2 : C) : C;
    const int cbase = second ? (bn - Nh) : bn;

#pragma unroll
    for (int i = 0; i < 2; i++) {
        int row = bm + wm * 32 + i * 16 + (lane >> 2);
#pragma unroll
        for (int n = 0; n < 8; n++) {
            int col = cbase + wn * 64 + n * 8 + (lane & 3) * 2;
            float v0 = acc[i][n][0], v1 = acc[i][n][1];
            float v2 = acc[i][n][2], v3 = acc[i][n][3];
            if (EPI == EPI_SILU || (EPI == EPI_DUAL && second)) {
                v0 = siluf(v0); v1 = siluf(v1); v2 = siluf(v2); v3 = siluf(v3);
            } else if (EPI == EPI_SP) {
                float b0 = bias[col], b1 = bias[col + 1];
                v0 = softplus_clip(v0 + b0); v1 = softplus_clip(v1 + b1);
                v2 = softplus_clip(v2 + b0); v3 = softplus_clip(v3 + b1);
            }
            *(float2*)&dst[(size_t)row * Nh + col]       = make_float2(v0, v1);
            *(float2*)&dst[(size_t)(row + 8) * Nh + col] = make_float2(v2, v3);
        }
    }
}

// ---------------- fp16 split expansion prepasses ------------------------------
template <int PAT>
__global__ __launch_bounds__(256)
void expand3_kernel(const float* __restrict__ in, __half* __restrict__ out,
                    int K, size_t total4)
{
    size_t i4 = (size_t)blockIdx.x * blockDim.x + threadIdx.x;
    if (i4 >= total4) return;
    size_t i = i4 * 4;
    float4 v = *(const float4*)(in + i);
    __half h[4], l[4];
    h_split(v.x, h[0], l[0]); h_split(v.y, h[1], l[1]);
    h_split(v.z, h[2], l[2]); h_split(v.w, h[3], l[3]);
    size_t r = i / K;
    int    k = (int)(i - r * K);
    __half* orow = out + r * (size_t)(3 * K);
    uint2 hp = *(uint2*)h, lp = *(uint2*)l;
    if (PAT == 0) {
        *(uint2*)(orow + k) = hp; *(uint2*)(orow + K + k) = hp; *(uint2*)(orow + 2 * K + k) = lp;
    } else {
        *(uint2*)(orow + k) = hp; *(uint2*)(orow + K + k) = lp; *(uint2*)(orow + 2 * K + k) = hp;
    }
}

template <int PAT>
__global__ __launch_bounds__(256)
void expand2_kernel(const float* __restrict__ in, __half* __restrict__ out,
                    int K, size_t total4)
{
    size_t i4 = (size_t)blockIdx.x * blockDim.x + threadIdx.x;
    if (i4 >= total4) return;
    size_t i = i4 * 4;
    float4 v = *(const float4*)(in + i);
    __half h[4], l[4];
    h_split(v.x, h[0], l[0]); h_split(v.y, h[1], l[1]);
    h_split(v.z, h[2], l[2]); h_split(v.w, h[3], l[3]);
    size_t r = i / K;
    int    k = (int)(i - r * K);
    __half* orow = out + r * (size_t)(2 * K);
    uint2 hp = *(uint2*)h, lp = *(uint2*)l;
    *(uint2*)(orow + k) = hp;
    if (PAT == 0) *(uint2*)(orow + K + k) = lp;
    else          *(uint2*)(orow + K + k) = hp;
}

__global__ __launch_bounds__(256)
void expand2_dual_kernel(const float* __restrict__ in1, const float* __restrict__ in2,
                         __half* __restrict__ out, int K, size_t half4)
{
    size_t i4 = (size_t)blockIdx.x * blockDim.x + threadIdx.x;
    if (i4 >= 2 * half4) return;
    const bool lo2 = (i4 >= half4);
    size_t j = (lo2 ? (i4 - half4) : i4) * 4;
    float4 v = *(const float4*)((lo2 ? in2 : in1) + j);
    __half h[4], l[4];
    h_split(v.x, h[0], l[0]); h_split(v.y, h[1], l[1]);
    h_split(v.z, h[2], l[2]); h_split(v.w, h[3], l[3]);
    size_t r = j / K + (lo2 ? DI : 0);
    int    k = (int)(j % K);
    __half* orow = out + r * (size_t)(2 * K);
    uint2 hp = *(uint2*)h;
    *(uint2*)(orow + k) = hp;
    *(uint2*)(orow + K + k) = hp;
}

// ---------------- small GEMM for B/C projections: N=32 ----------------------
__global__ __launch_bounds__(256)
void sgemm_bc_kernel(const float* __restrict__ A, const float* __restrict__ WB,
                     const float* __restrict__ WC, float* __restrict__ C,
                     int M, int K)
{
    const int BM = 64, BK = 8;
    __shared__ __align__(16) float As[BK][BM];
    __shared__ __align__(16) float Ws[BK][32];

    const int tid = threadIdx.x;
    const int bm  = blockIdx.x * BM;
    const int tx  = tid & 31;
    const int ty  = tid >> 5;

    const bool la = (tid < 128);
    const int  ar = tid >> 1, ac = (tid & 1) * 4;
    const bool lw = (tid >= 128 && tid < 192);
    const int  wt = tid - 128, wr = wt >> 1, wc = (wt & 1) * 4;

    const float* Ap = A + (size_t)(bm + ar) * K + ac;
    const float* Wp = (wr < 16 ? WB + (size_t)wr * K : WC + (size_t)(wr - 16) * K) + wc;

    float acc[8];
#pragma unroll
    for (int i = 0; i < 8; i++) acc[i] = 0.0f;

    float4 aR = la ? *(const float4*)Ap : make_float4(0, 0, 0, 0);
    float4 wR = lw ? *(const float4*)Wp : make_float4(0, 0, 0, 0);

    const int nsteps = K / BK;
    for (int s = 0; s < nsteps; s++) {
        if (la) {
            As[ac + 0][ar] = aR.x; As[ac + 1][ar] = aR.y;
            As[ac + 2][ar] = aR.z; As[ac + 3][ar] = aR.w;
        }
        if (lw) {
            Ws[wc + 0][wr] = wR.x; Ws[wc + 1][wr] = wR.y;
            Ws[wc + 2][wr] = wR.z; Ws[wc + 3][wr] = wR.w;
        }
        __syncthreads();
        if (s + 1 < nsteps) {
            if (la) aR = *(const float4*)(Ap + (size_t)(s + 1) * BK);
            if (lw) wR = *(const float4*)(Wp + (size_t)(s + 1) * BK);
        }
#pragma unroll
        for (int k = 0; k < BK; k++) {
            float wf = Ws[k][tx];
            float4 a0 = *(const float4*)&As[k][ty * 8];
            float4 a1 = *(const float4*)&As[k][ty * 8 + 4];
            acc[0] = fmaf(a0.x, wf, acc[0]);
            acc[1] = fmaf(a0.y, wf, acc[1]);
            acc[2] = fmaf(a0.z, wf, acc[2]);
            acc[3] = fmaf(a0.w, wf, acc[3]);
            acc[4] = fmaf(a1.x, wf, acc[4]);
            acc[5] = fmaf(a1.y, wf, acc[5]);
            acc[6] = fmaf(a1.z, wf, acc[6]);
            acc[7] = fmaf(a1.w, wf, acc[7]);
        }
        __syncthreads();
    }
#pragma unroll
    for (int i = 0; i < 8; i++)
        C[(size_t)(bm + ty * 8 + i) * 32 + tx] = acc[i];
}

// ---------------- causal depthwise conv + silu + fp16 3-term split ----------
__global__ __launch_bounds__(256)
void conv_silu_split_kernel(const float* __restrict__ left,
                            const float* __restrict__ cw,
                            const float* __restrict__ cb,
                            float* __restrict__ xl,
                            __half* __restrict__ xl3)
{
    size_t t = (size_t)blockIdx.x * blockDim.x + threadIdx.x;
    if (t >= (size_t)MROWS * DI / 4) return;
    int d = (int)((t * 4) % DI);
    size_t row = (t * 4) / DI;
    int l = (int)(row % LL);

    const float4 cbv = *(const float4*)&cb[d];
    float acc[4] = {cbv.x, cbv.y, cbv.z, cbv.w};
    float4 w0 = *(const float4*)&cw[(size_t)d * DC];
    float4 w1 = *(const float4*)&cw[(size_t)(d + 1) * DC];
    float4 w2 = *(const float4*)&cw[(size_t)(d + 2) * DC];
    float4 w3 = *(const float4*)&cw[(size_t)(d + 3) * DC];
    const float* wv[4] = {&w0.x, &w1.x, &w2.x, &w3.x};

#pragma unroll
    for (int j = 0; j < DC; j++) {
        int ls = l + j - (DC - 1);
        if (ls >= 0) {
            const float4 v = *(const float4*)&left[(row + (size_t)(j - (DC - 1))) * DI + d];
#pragma unroll
            for (int q = 0; q < 4; q++)
                acc[q] = fmaf(wv[q][j], (&v.x)[q], acc[q]);
        }
    }
    __half h[4], lo[4];
    float o[4];
#pragma unroll
    for (int q = 0; q < 4; q++) {
        o[q] = siluf(acc[q]);
        h_split(o[q], h[q], lo[q]);
    }
    *(float4*)&xl[row * DI + d] = make_float4(o[0], o[1], o[2], o[3]);
    __half* orow = xl3 + row * (size_t)(3 * DI);
    *(uint2*)(orow + d) = *(uint2*)h;
    *(uint2*)(orow + DI + d) = *(uint2*)h;
    *(uint2*)(orow + 2 * DI + d) = *(uint2*)lo;
}

// ---------------- selective scan: 8 threads per (b,d) channel, MLP=8 --------
// 8-deep register ring buffer; per-element arithmetic order unchanged
// (bitwise-identical y). R12 validated the latency model at MLP=4 (-113us).
__global__ __launch_bounds__(256)
void scan_kernel(const float* __restrict__ delta, const float* __restrict__ xl,
                 const float* __restrict__ BC, const float* __restrict__ A_log,
                 float* __restrict__ y)
{
    int g   = blockIdx.x * blockDim.x + threadIdx.x;
    int grp = g & 7;
    int ch  = g >> 3;
    int d   = ch % DI;
    int b   = ch / DI;

    float Av0, Av1;
    Av0 = -log1pf(expf(A_log[grp * 2 + 0]));
    Av1 = -log1pf(expf(A_log[grp * 2 + 1]));

    float h0 = 0.f, h1 = 0.f;
    size_t rb = (size_t)b * LL;

    const float* dp = delta + rb * DI + d;
    const float* xp = xl    + rb * DI + d;
    const float* bp = BC + rb * 32 + grp * 2;
    float*       yp = y  + rb * DI + d;

    float  dtb[8], xtb[8];
    float2 Bb[8], Cb[8];
#pragma unroll
    for (int i = 0; i < 8; i++) {
        dtb[i] = __ldg(dp + (size_t)i * DI);
        xtb[i] = __ldg(xp + (size_t)i * DI);
        Bb[i]  = *(const float2*)(bp + (size_t)i * 32);
        Cb[i]  = *(const float2*)(bp + (size_t)i * 32 + 16);
    }

#pragma unroll 8
    for (int l = 0; l < LL; l++) {
        const int s = l & 7;
        float  dt = dtb[s], xt = xtb[s];
        float2 Bv = Bb[s],  Cv = Cb[s];

        if (l + 8 < LL) {
            dtb[s] = __ldg(dp + (size_t)(l + 8) * DI);
            xtb[s] = __ldg(xp + (size_t)(l + 8) * DI);
            Bb[s]  = *(const float2*)(bp + (size_t)(l + 8) * 32);
            Cb[s]  = *(const float2*)(bp + (size_t)(l + 8) * 32 + 16);
        }

        float w  = dt * xt;
        float a0 = __expf(dt * Av0);
        float a1 = __expf(dt * Av1);
        h0 = fmaf(a0, h0, w * Bv.x);
        h1 = fmaf(a1, h1, w * Bv.y);
        float p = h0 * Cv.x + h1 * Cv.y;
        p += __shfl_xor_sync(0xffffffffu, p, 1);
        p += __shfl_xor_sync(0xffffffffu, p, 2);
        p += __shfl_xor_sync(0xffffffffu, p, 4);
        if (grp == 0) yp[(size_t)l * DI] = p;
    }
}

// ---------------- gated layernorm -> fp16 2-term A planes -------------------
__global__ __launch_bounds__(256)
void ln_gate_split_kernel(const float* __restrict__ y, const float* __restrict__ gate,
                          const float* __restrict__ lng, const float* __restrict__ lnb,
                          __half* __restrict__ out2)
{
    int row = blockIdx.x;
    int tid = threadIdx.x;
    const float* yr = y    + (size_t)row * DI;
    const float* gr = gate + (size_t)row * DI;

    float v[8];
    float s = 0.f, sq = 0.f;
#pragma unroll
    for (int i = 0; i < 8; i++) {
        int c = tid + i * 256;
        v[i] = yr[c] * gr[c];
        s  += v[i];
        sq += v[i] * v[i];
    }
    __shared__ float rs[8], rq[8];
#pragma unroll
    for (int o = 16; o > 0; o >>= 1) {
        s  += __shfl_xor_sync(0xffffffffu, s,  o);
        sq += __shfl_xor_sync(0xffffffffu, sq, o);
    }
    if ((tid & 31) == 0) { rs[tid >> 5] = s; rq[tid >> 5] = sq; }
    __syncthreads();
    float ts = 0.f, tq = 0.f;
#pragma unroll
    for (int w = 0; w < 8; w++) { ts += rs[w]; tq += rq[w]; }

    float mu  = ts * (1.0f / DI);
    float var = tq * (1.0f / DI) - mu * mu;
    float inv = rsqrtf(var + 1e-5f);

    __half* orow = out2 + (size_t)row * (2 * DI);
#pragma unroll
    for (int i = 0; i < 8; i++) {
        int c = tid + i * 256;
        float o = (v[i] - mu) * inv * lng[c] + lnb[c];
        __half hi, lo;
        h_split(o, hi, lo);
        orow[c] = hi; orow[DI + c] = lo;
    }
}

// ---------------- launch --------------------------------------------------
extern "C" void kernel_launch(void* const* d_in, const int* in_sizes, int n_in,
                              void* d_out, int out_size)
{
    const float* x       = (const float*)d_in[0];
    const float* W_left  = (const float*)d_in[1];
    const float* conv_w  = (const float*)d_in[2];
    const float* conv_b  = (const float*)d_in[3];
    const float* W_delta = (const float*)d_in[4];
    const float* b_delta = (const float*)d_in[5];
    const float* W_B     = (const float*)d_in[6];
    const float* W_C     = (const float*)d_in[7];
    const float* A_log   = (const float*)d_in[8];
    const float* W_right = (const float*)d_in[9];
    const float* ln_g    = (const float*)d_in[10];
    const float* ln_b    = (const float*)d_in[11];
    const float* W_out   = (const float*)d_in[12];
    float*       out     = (float*)d_out;

    float *left, *xl, *delta, *gate, *y, *BC;
    __half *x2, *wlr2, *wd3, *wo2, *xl3;
    cudaGetSymbolAddress((void**)&left,  g_left);
    cudaGetSymbolAddress((void**)&xl,    g_xl);
    cudaGetSymbolAddress((void**)&delta, g_delta);
    cudaGetSymbolAddress((void**)&gate,  g_gate);
    cudaGetSymbolAddress((void**)&y,     g_y);
    cudaGetSymbolAddress((void**)&BC,    g_BC);
    cudaGetSymbolAddress((void**)&x2,    g_x2);
    cudaGetSymbolAddress((void**)&wlr2,  g_wlr2);
    cudaGetSymbolAddress((void**)&wd3,   g_wd3);
    cudaGetSymbolAddress((void**)&wo2,   g_wo2);
    cudaGetSymbolAddress((void**)&xl3,   g_xl3);

    cudaFuncSetAttribute(hgemm_kernel<EPI_NONE>, cudaFuncAttributeMaxDynamicSharedMemorySize, HG_SMEM);
    cudaFuncSetAttribute(hgemm_kernel<EPI_DUAL>, cudaFuncAttributeMaxDynamicSharedMemorySize, HG_SMEM);
    cudaFuncSetAttribute(hgemm_kernel<EPI_SP>,   cudaFuncAttributeMaxDynamicSharedMemorySize, HG_SMEM);

    size_t n4;

    // W_delta 3-term expansion
    n4 = (size_t)DI * DI / 4;
    expand3_kernel<1><<<(int)((n4 + 255) / 256), 256>>>(W_delta, wd3, DI, n4);

    // x 2-term expansion
    n4 = (size_t)MROWS * DM / 4;
    expand2_kernel<0><<<(int)((n4 + 255) / 256), 256>>>(x, x2, DM, n4);

    // merged [W_left; W_right] 2-term expansion
    n4 = (size_t)DI * DM / 4;
    expand2_dual_kernel<<<(int)((2 * n4 + 255) / 256), 256>>>(W_left, W_right, wlr2, DM, n4);

    // merged [left | gate] = x @ [W_left;W_right]^T  [8192 x 4096], K2=2048
    hgemm_kernel<EPI_DUAL><<<dim3(2 * DI / 128, MROWS / 128), 256, HG_SMEM>>>(
        x2, wlr2, nullptr, left, gate, MROWS, 2 * DI, 2 * DM);

    // xl = silu(causal_conv(left)) + fp16 3-term split into xl3
    conv_silu_split_kernel<<<(int)(((size_t)MROWS * DI / 4 + 255) / 256), 256>>>(
        left, conv_w, conv_b, xl, xl3);

    // delta GEMM, K3=6144, 3-term, BN=128
    hgemm_kernel<EPI_SP><<<dim3(DI / 128, MROWS / 128), 256, HG_SMEM>>>(
        xl3, wd3, b_delta, delta, nullptr, MROWS, DI, 3 * DI);

    // [Bm|Cm] = xl @ [W_B;W_C]^T  [8192 x 32], K=2048 (fp32 SIMT, pack fused)
    sgemm_bc_kernel<<<MROWS / 64, 256>>>(xl, W_B, W_C, BC, MROWS, DI);

    // selective scan (8 threads / channel, MLP=8 prefetch)
    scan_kernel<<<(BB * DI * 8) / 256, 256>>>(delta, xl, BC, A_log, y);

    // LN(y*gate) -> fp16 2-term A planes (reuse xl3 buffer)
    ln_gate_split_kernel<<<MROWS, 256>>>(y, gate, ln_g, ln_b, xl3);

    // W_out 2-term expansion
    n4 = (size_t)DM * DI / 4;
    expand2_kernel<1><<<(int)((n4 + 255) / 256), 256>>>(W_out, wo2, DI, n4);

    // out = ln_out @ W_out^T  [8192 x 1024], K2=4096, 2-term
    hgemm_kernel<EPI_NONE><<<dim3(DM / 128, MROWS / 128), 256, HG_SMEM>>>(
        xl3, wo2, nullptr, out, nullptr, MROWS, DM, 2 * DI);
}

// round 15
// speedup vs baseline: 1.0619x; 1.0233x over previous
#include <cuda_runtime.h>
#include <cuda_fp16.h>
#include <math.h>
#include <stdint.h>

// ---------------- Problem constants ----------------
#define BB      4
#define LL      2048
#define DM      1024
#define DI      2048
#define DC      4
#define MROWS   (BB * LL)          // 8192 token rows

// ---------------- Scratch (device globals; no cudaMalloc allowed) ----------
__device__ float g_left [(size_t)MROWS * DI];   // left; later split-K partial 1
__device__ float g_xl   [(size_t)MROWS * DI];
__device__ float g_delta[(size_t)MROWS * DI];
__device__ float g_gate [(size_t)MROWS * DI];
__device__ float g_y    [(size_t)MROWS * DI];   // split-K partial 0; later scan out
__device__ float g_BC   [(size_t)MROWS * 32];
// fp16 split planes.
__device__ __align__(16) __half g_x2  [(size_t)MROWS * 2 * DM];     // x, 2-term A
__device__ __align__(16) __half g_wlr2[(size_t)2 * DI * 2 * DM];    // [W_left; W_right], 2-term B
__device__ __align__(16) __half g_wd3 [(size_t)DI * 3 * DI];        // W_delta, 3-term B
__device__ __align__(16) __half g_wo2 [(size_t)DM * 2 * DI];        // W_out, 2-term B
__device__ __align__(16) __half g_xl3 [(size_t)MROWS * 3 * DI];     // xl 3-term A; later LN-out 2-term A

// ---------------- scalar helpers ----------------
__device__ __forceinline__ float siluf(float x) { return x / (1.0f + __expf(-x)); }
__device__ __forceinline__ float softplus_clip(float x) {
    float sp = (x > 20.0f) ? x : log1pf(__expf(x));
    return fminf(fmaxf(sp, 1e-4f), 10.0f);
}
__device__ __forceinline__ void h_split(float v, __half& hi, __half& lo) {
    hi = __float2half_rn(v);
    lo = __float2half_rn(v - __half2float(hi));
}

// ---------------- PTX helpers (portable sm_80-class only) --------------------
__device__ __forceinline__ uint32_t smem_u32(const void* p) {
    uint32_t a;
    asm("{ .reg .u64 t; cvta.to.shared.u64 t, %1; cvt.u32.u64 %0, t; }" : "=r"(a) : "l"(p));
    return a;
}
__device__ __forceinline__ void cp_async16(uint32_t dst, const void* src) {
    asm volatile("cp.async.cg.shared.global [%0], [%1], 16;" :: "r"(dst), "l"(src) : "memory");
}
__device__ __forceinline__ void cp_commit() {
    asm volatile("cp.async.commit_group;" ::: "memory");
}
template <int N>
__device__ __forceinline__ void cp_wait_group() {
    asm volatile("cp.async.wait_group %0;" :: "n"(N) : "memory");
}
__device__ __forceinline__ void ldmx4(uint32_t& r0, uint32_t& r1, uint32_t& r2, uint32_t& r3,
                                      uint32_t addr) {
    asm volatile("ldmatrix.sync.aligned.m8n8.x4.shared.b16 {%0,%1,%2,%3}, [%4];"
                 : "=r"(r0), "=r"(r1), "=r"(r2), "=r"(r3) : "r"(addr));
}
__device__ __forceinline__ void mma16816(float* d, const uint32_t* a,
                                         uint32_t b0, uint32_t b1) {
    asm volatile(
        "mma.sync.aligned.m16n8k16.row.col.f32.f16.f16.f32 "
        "{%0,%1,%2,%3}, {%4,%5,%6,%7}, {%8,%9}, {%0,%1,%2,%3};"
        : "+f"(d[0]), "+f"(d[1]), "+f"(d[2]), "+f"(d[3])
        : "r"(a[0]), "r"(a[1]), "r"(a[2]), "r"(a[3]), "r"(b0), "r"(b1));
}

// ---------------- fp16 GEMM (BN=128):  C[M,N] = A[M,Kp] @ W[N,Kp]^T --------
// BM=128, BN=128, BK=64 halves, 3-stage cp.async, 256 threads, 2 CTAs/SM.
// EPI_RAW: split-K slice (blockIdx.z selects K half) writing raw fp32 partials
// to C (z=0) / C2 (z=1).
#define EPI_NONE 0
#define EPI_SILU 1
#define EPI_SP   2
#define EPI_DUAL 3
#define EPI_RAW  4

#define HG_STAGES 3
#define HG_STG    32768                 // 16KB A + 16KB B per stage
#define HG_SMEM   (HG_STAGES * HG_STG)  // 96KB

template <int EPI>
__global__ __launch_bounds__(256, 2)
void hgemm_kernel(const __half* __restrict__ A, const __half* __restrict__ W,
                  const float* __restrict__ bias, float* __restrict__ C,
                  float* __restrict__ C2,
                  int M, int N, int K3)
{
    extern __shared__ char smem[];
    const uint32_t sbase = smem_u32(smem);

    const int tid  = threadIdx.x;
    const int lane = tid & 31;
    const int wid  = tid >> 5;
    const int wm   = wid & 3;           // 0..3
    const int wn   = wid >> 2;          // 0..1
    const int bm   = blockIdx.y * 128;
    const int bn   = blockIdx.x * 128;
    const int kz   = (EPI == EPI_RAW) ? blockIdx.z : 0;
    const int Ksl  = (EPI == EPI_RAW) ? (K3 >> 1) : K3;   // K per slice
    const int nch  = Ksl >> 6;

    const int lr  = tid >> 1;
    const int lc0 = (tid & 1) * 4;
    const __half* gA = A + (size_t)(bm + lr) * K3 + (size_t)kz * Ksl + lc0 * 8;
    const __half* gW = W + (size_t)(bn + lr) * K3 + (size_t)kz * Ksl + lc0 * 8;
    uint32_t soff[4];
#pragma unroll
    for (int j = 0; j < 4; j++)
        soff[j] = (uint32_t)(lr * 128 + (((lc0 + j) ^ (lr & 7)) << 4));

    float acc[2][8][4];
#pragma unroll
    for (int i = 0; i < 2; i++)
#pragma unroll
        for (int n = 0; n < 8; n++)
#pragma unroll
            for (int q = 0; q < 4; q++) acc[i][n][q] = 0.0f;

    const int alr = lane & 15;
    const int ac8 = lane >> 4;

#pragma unroll
    for (int s = 0; s < HG_STAGES - 1; s++) {
        if (s < nch) {
            uint32_t sa = sbase + s * HG_STG;
            const __half* ga = gA + (size_t)s * 64;
            const __half* gw = gW + (size_t)s * 64;
#pragma unroll
            for (int j = 0; j < 4; j++) {
                cp_async16(sa + soff[j], ga + j * 8);
                cp_async16(sa + 16384 + soff[j], gw + j * 8);
            }
            cp_commit();
        }
    }

    for (int c = 0; c < nch; c++) {
        cp_wait_group<HG_STAGES - 2>();
        __syncthreads();

        int nc = c + HG_STAGES - 1;
        if (nc < nch) {
            uint32_t sa = sbase + (nc % HG_STAGES) * HG_STG;
            const __half* ga = gA + (size_t)nc * 64;
            const __half* gw = gW + (size_t)nc * 64;
#pragma unroll
            for (int j = 0; j < 4; j++) {
                cp_async16(sa + soff[j], ga + j * 8);
                cp_async16(sa + 16384 + soff[j], gw + j * 8);
            }
            cp_commit();
        }

        const uint32_t sa = sbase + (c % HG_STAGES) * HG_STG;
        const uint32_t sb = sa + 16384;
#pragma unroll
        for (int kk = 0; kk < 4; kk++) {
            const int c8 = kk * 2 + ac8;
            uint32_t a[2][4];
#pragma unroll
            for (int i = 0; i < 2; i++) {
                int row = wm * 32 + i * 16 + alr;
                ldmx4(a[i][0], a[i][1], a[i][2], a[i][3],
                      sa + row * 128 + ((c8 ^ (row & 7)) << 4));
            }
            uint32_t b[8][2];
#pragma unroll
            for (int j = 0; j < 4; j++) {
                int row = wn * 64 + j * 16 + alr;
                uint32_t r0, r1, r2, r3;
                ldmx4(r0, r1, r2, r3, sb + row * 128 + ((c8 ^ (row & 7)) << 4));
                b[2 * j][0] = r0; b[2 * j + 1][0] = r1;
                b[2 * j][1] = r2; b[2 * j + 1][1] = r3;
            }
#pragma unroll
            for (int i = 0; i < 2; i++)
#pragma unroll
                for (int n = 0; n < 8; n++)
                    mma16816(acc[i][n], a[i], b[n][0], b[n][1]);
        }
    }

    // ---------------- epilogue ----------------
    const int Nh = (EPI == EPI_DUAL) ? (N >> 1) : N;
    const bool second = (EPI == EPI_DUAL) && (bn >= Nh);
    float* dst = (EPI == EPI_DUAL) ? (second ? C2 : C)
               : (EPI == EPI_RAW)  ? (kz ? C2 : C) : C;
    const int cbase = second ? (bn - Nh) : bn;

#pragma unroll
    for (int i = 0; i < 2; i++) {
        int row = bm + wm * 32 + i * 16 + (lane >> 2);
#pragma unroll
        for (int n = 0; n < 8; n++) {
            int col = cbase + wn * 64 + n * 8 + (lane & 3) * 2;
            float v0 = acc[i][n][0], v1 = acc[i][n][1];
            float v2 = acc[i][n][2], v3 = acc[i][n][3];
            if (EPI == EPI_SILU || (EPI == EPI_DUAL && second)) {
                v0 = siluf(v0); v1 = siluf(v1); v2 = siluf(v2); v3 = siluf(v3);
            } else if (EPI == EPI_SP) {
                float b0 = bias[col], b1 = bias[col + 1];
                v0 = softplus_clip(v0 + b0); v1 = softplus_clip(v1 + b1);
                v2 = softplus_clip(v2 + b0); v3 = softplus_clip(v3 + b1);
            }
            *(float2*)&dst[(size_t)row * Nh + col]       = make_float2(v0, v1);
            *(float2*)&dst[(size_t)(row + 8) * Nh + col] = make_float2(v2, v3);
        }
    }
}

// ---------------- split-K reduction + bias + softplus for delta -------------
__global__ __launch_bounds__(256)
void reduce_sp_kernel(const float* __restrict__ p0, const float* __restrict__ p1,
                      const float* __restrict__ bias, float* __restrict__ out,
                      size_t total4)
{
    size_t i4 = (size_t)blockIdx.x * blockDim.x + threadIdx.x;
    if (i4 >= total4) return;
    size_t i = i4 * 4;
    int col = (int)(i % DI);
    float4 a = *(const float4*)(p0 + i);
    float4 b = *(const float4*)(p1 + i);
    float4 bv = *(const float4*)(bias + col);
    float4 o;
    o.x = softplus_clip(a.x + b.x + bv.x);
    o.y = softplus_clip(a.y + b.y + bv.y);
    o.z = softplus_clip(a.z + b.z + bv.z);
    o.w = softplus_clip(a.w + b.w + bv.w);
    *(float4*)(out + i) = o;
}

// ---------------- fp16 split expansion prepasses ------------------------------
template <int PAT>
__global__ __launch_bounds__(256)
void expand3_kernel(const float* __restrict__ in, __half* __restrict__ out,
                    int K, size_t total4)
{
    size_t i4 = (size_t)blockIdx.x * blockDim.x + threadIdx.x;
    if (i4 >= total4) return;
    size_t i = i4 * 4;
    float4 v = *(const float4*)(in + i);
    __half h[4], l[4];
    h_split(v.x, h[0], l[0]); h_split(v.y, h[1], l[1]);
    h_split(v.z, h[2], l[2]); h_split(v.w, h[3], l[3]);
    size_t r = i / K;
    int    k = (int)(i - r * K);
    __half* orow = out + r * (size_t)(3 * K);
    uint2 hp = *(uint2*)h, lp = *(uint2*)l;
    if (PAT == 0) {
        *(uint2*)(orow + k) = hp; *(uint2*)(orow + K + k) = hp; *(uint2*)(orow + 2 * K + k) = lp;
    } else {
        *(uint2*)(orow + k) = hp; *(uint2*)(orow + K + k) = lp; *(uint2*)(orow + 2 * K + k) = hp;
    }
}

template <int PAT>
__global__ __launch_bounds__(256)
void expand2_kernel(const float* __restrict__ in, __half* __restrict__ out,
                    int K, size_t total4)
{
    size_t i4 = (size_t)blockIdx.x * blockDim.x + threadIdx.x;
    if (i4 >= total4) return;
    size_t i = i4 * 4;
    float4 v = *(const float4*)(in + i);
    __half h[4], l[4];
    h_split(v.x, h[0], l[0]); h_split(v.y, h[1], l[1]);
    h_split(v.z, h[2], l[2]); h_split(v.w, h[3], l[3]);
    size_t r = i / K;
    int    k = (int)(i - r * K);
    __half* orow = out + r * (size_t)(2 * K);
    uint2 hp = *(uint2*)h, lp = *(uint2*)l;
    *(uint2*)(orow + k) = hp;
    if (PAT == 0) *(uint2*)(orow + K + k) = lp;
    else          *(uint2*)(orow + K + k) = hp;
}

__global__ __launch_bounds__(256)
void expand2_dual_kernel(const float* __restrict__ in1, const float* __restrict__ in2,
                         __half* __restrict__ out, int K, size_t half4)
{
    size_t i4 = (size_t)blockIdx.x * blockDim.x + threadIdx.x;
    if (i4 >= 2 * half4) return;
    const bool lo2 = (i4 >= half4);
    size_t j = (lo2 ? (i4 - half4) : i4) * 4;
    float4 v = *(const float4*)((lo2 ? in2 : in1) + j);
    __half h[4], l[4];
    h_split(v.x, h[0], l[0]); h_split(v.y, h[1], l[1]);
    h_split(v.z, h[2], l[2]); h_split(v.w, h[3], l[3]);
    size_t r = j / K + (lo2 ? DI : 0);
    int    k = (int)(j % K);
    __half* orow = out + r * (size_t)(2 * K);
    uint2 hp = *(uint2*)h;
    *(uint2*)(orow + k) = hp;
    *(uint2*)(orow + K + k) = hp;
}

// ---------------- small GEMM for B/C projections: N=32 ----------------------
__global__ __launch_bounds__(256)
void sgemm_bc_kernel(const float* __restrict__ A, const float* __restrict__ WB,
                     const float* __restrict__ WC, float* __restrict__ C,
                     int M, int K)
{
    const int BM = 64, BK = 8;
    __shared__ __align__(16) float As[BK][BM];
    __shared__ __align__(16) float Ws[BK][32];

    const int tid = threadIdx.x;
    const int bm  = blockIdx.x * BM;
    const int tx  = tid & 31;
    const int ty  = tid >> 5;

    const bool la = (tid < 128);
    const int  ar = tid >> 1, ac = (tid & 1) * 4;
    const bool lw = (tid >= 128 && tid < 192);
    const int  wt = tid - 128, wr = wt >> 1, wc = (wt & 1) * 4;

    const float* Ap = A + (size_t)(bm + ar) * K + ac;
    const float* Wp = (wr < 16 ? WB + (size_t)wr * K : WC + (size_t)(wr - 16) * K) + wc;

    float acc[8];
#pragma unroll
    for (int i = 0; i < 8; i++) acc[i] = 0.0f;

    float4 aR = la ? *(const float4*)Ap : make_float4(0, 0, 0, 0);
    float4 wR = lw ? *(const float4*)Wp : make_float4(0, 0, 0, 0);

    const int nsteps = K / BK;
    for (int s = 0; s < nsteps; s++) {
        if (la) {
            As[ac + 0][ar] = aR.x; As[ac + 1][ar] = aR.y;
            As[ac + 2][ar] = aR.z; As[ac + 3][ar] = aR.w;
        }
        if (lw) {
            Ws[wc + 0][wr] = wR.x; Ws[wc + 1][wr] = wR.y;
            Ws[wc + 2][wr] = wR.z; Ws[wc + 3][wr] = wR.w;
        }
        __syncthreads();
        if (s + 1 < nsteps) {
            if (la) aR = *(const float4*)(Ap + (size_t)(s + 1) * BK);
            if (lw) wR = *(const float4*)(Wp + (size_t)(s + 1) * BK);
        }
#pragma unroll
        for (int k = 0; k < BK; k++) {
            float wf = Ws[k][tx];
            float4 a0 = *(const float4*)&As[k][ty * 8];
            float4 a1 = *(const float4*)&As[k][ty * 8 + 4];
            acc[0] = fmaf(a0.x, wf, acc[0]);
            acc[1] = fmaf(a0.y, wf, acc[1]);
            acc[2] = fmaf(a0.z, wf, acc[2]);
            acc[3] = fmaf(a0.w, wf, acc[3]);
            acc[4] = fmaf(a1.x, wf, acc[4]);
            acc[5] = fmaf(a1.y, wf, acc[5]);
            acc[6] = fmaf(a1.z, wf, acc[6]);
            acc[7] = fmaf(a1.w, wf, acc[7]);
        }
        __syncthreads();
    }
#pragma unroll
    for (int i = 0; i < 8; i++)
        C[(size_t)(bm + ty * 8 + i) * 32 + tx] = acc[i];
}

// ---------------- causal depthwise conv + silu + fp16 3-term split ----------
__global__ __launch_bounds__(256)
void conv_silu_split_kernel(const float* __restrict__ left,
                            const float* __restrict__ cw,
                            const float* __restrict__ cb,
                            float* __restrict__ xl,
                            __half* __restrict__ xl3)
{
    size_t t = (size_t)blockIdx.x * blockDim.x + threadIdx.x;
    if (t >= (size_t)MROWS * DI / 4) return;
    int d = (int)((t * 4) % DI);
    size_t row = (t * 4) / DI;
    int l = (int)(row % LL);

    const float4 cbv = *(const float4*)&cb[d];
    float acc[4] = {cbv.x, cbv.y, cbv.z, cbv.w};
    float4 w0 = *(const float4*)&cw[(size_t)d * DC];
    float4 w1 = *(const float4*)&cw[(size_t)(d + 1) * DC];
    float4 w2 = *(const float4*)&cw[(size_t)(d + 2) * DC];
    float4 w3 = *(const float4*)&cw[(size_t)(d + 3) * DC];
    const float* wv[4] = {&w0.x, &w1.x, &w2.x, &w3.x};

#pragma unroll
    for (int j = 0; j < DC; j++) {
        int ls = l + j - (DC - 1);
        if (ls >= 0) {
            const float4 v = *(const float4*)&left[(row + (size_t)(j - (DC - 1))) * DI + d];
#pragma unroll
            for (int q = 0; q < 4; q++)
                acc[q] = fmaf(wv[q][j], (&v.x)[q], acc[q]);
        }
    }
    __half h[4], lo[4];
    float o[4];
#pragma unroll
    for (int q = 0; q < 4; q++) {
        o[q] = siluf(acc[q]);
        h_split(o[q], h[q], lo[q]);
    }
    *(float4*)&xl[row * DI + d] = make_float4(o[0], o[1], o[2], o[3]);
    __half* orow = xl3 + row * (size_t)(3 * DI);
    *(uint2*)(orow + d) = *(uint2*)h;
    *(uint2*)(orow + DI + d) = *(uint2*)h;
    *(uint2*)(orow + 2 * DI + d) = *(uint2*)lo;
}

// ---------------- selective scan: 8 threads per (b,d) channel, MLP=16 -------
// 16-deep register ring buffer; per-element arithmetic order unchanged.
__global__ __launch_bounds__(256)
void scan_kernel(const float* __restrict__ delta, const float* __restrict__ xl,
                 const float* __restrict__ BC, const float* __restrict__ A_log,
                 float* __restrict__ y)
{
    int g   = blockIdx.x * blockDim.x + threadIdx.x;
    int grp = g & 7;
    int ch  = g >> 3;
    int d   = ch % DI;
    int b   = ch / DI;

    float Av0, Av1;
    Av0 = -log1pf(expf(A_log[grp * 2 + 0]));
    Av1 = -log1pf(expf(A_log[grp * 2 + 1]));

    float h0 = 0.f, h1 = 0.f;
    size_t rb = (size_t)b * LL;

    const float* dp = delta + rb * DI + d;
    const float* xp = xl    + rb * DI + d;
    const float* bp = BC + rb * 32 + grp * 2;
    float*       yp = y  + rb * DI + d;

    float  dtb[16], xtb[16];
    float2 Bb[16], Cb[16];
#pragma unroll
    for (int i = 0; i < 16; i++) {
        dtb[i] = __ldg(dp + (size_t)i * DI);
        xtb[i] = __ldg(xp + (size_t)i * DI);
        Bb[i]  = *(const float2*)(bp + (size_t)i * 32);
        Cb[i]  = *(const float2*)(bp + (size_t)i * 32 + 16);
    }

#pragma unroll 16
    for (int l = 0; l < LL; l++) {
        const int s = l & 15;
        float  dt = dtb[s], xt = xtb[s];
        float2 Bv = Bb[s],  Cv = Cb[s];

        if (l + 16 < LL) {
            dtb[s] = __ldg(dp + (size_t)(l + 16) * DI);
            xtb[s] = __ldg(xp + (size_t)(l + 16) * DI);
            Bb[s]  = *(const float2*)(bp + (size_t)(l + 16) * 32);
            Cb[s]  = *(const float2*)(bp + (size_t)(l + 16) * 32 + 16);
        }

        float w  = dt * xt;
        float a0 = __expf(dt * Av0);
        float a1 = __expf(dt * Av1);
        h0 = fmaf(a0, h0, w * Bv.x);
        h1 = fmaf(a1, h1, w * Bv.y);
        float p = h0 * Cv.x + h1 * Cv.y;
        p += __shfl_xor_sync(0xffffffffu, p, 1);
        p += __shfl_xor_sync(0xffffffffu, p, 2);
        p += __shfl_xor_sync(0xffffffffu, p, 4);
        if (grp == 0) yp[(size_t)l * DI] = p;
    }
}

// ---------------- gated layernorm -> fp16 2-term A planes -------------------
__global__ __launch_bounds__(256)
void ln_gate_split_kernel(const float* __restrict__ y, const float* __restrict__ gate,
                          const float* __restrict__ lng, const float* __restrict__ lnb,
                          __half* __restrict__ out2)
{
    int row = blockIdx.x;
    int tid = threadIdx.x;
    const float* yr = y    + (size_t)row * DI;
    const float* gr = gate + (size_t)row * DI;

    float v[8];
    float s = 0.f, sq = 0.f;
#pragma unroll
    for (int i = 0; i < 8; i++) {
        int c = tid + i * 256;
        v[i] = yr[c] * gr[c];
        s  += v[i];
        sq += v[i] * v[i];
    }
    __shared__ float rs[8], rq[8];
#pragma unroll
    for (int o = 16; o > 0; o >>= 1) {
        s  += __shfl_xor_sync(0xffffffffu, s,  o);
        sq += __shfl_xor_sync(0xffffffffu, sq, o);
    }
    if ((tid & 31) == 0) { rs[tid >> 5] = s; rq[tid >> 5] = sq; }
    __syncthreads();
    float ts = 0.f, tq = 0.f;
#pragma unroll
    for (int w = 0; w < 8; w++) { ts += rs[w]; tq += rq[w]; }

    float mu  = ts * (1.0f / DI);
    float var = tq * (1.0f / DI) - mu * mu;
    float inv = rsqrtf(var + 1e-5f);

    __half* orow = out2 + (size_t)row * (2 * DI);
#pragma unroll
    for (int i = 0; i < 8; i++) {
        int c = tid + i * 256;
        float o = (v[i] - mu) * inv * lng[c] + lnb[c];
        __half hi, lo;
        h_split(o, hi, lo);
        orow[c] = hi; orow[DI + c] = lo;
    }
}

// ---------------- launch --------------------------------------------------
extern "C" void kernel_launch(void* const* d_in, const int* in_sizes, int n_in,
                              void* d_out, int out_size)
{
    const float* x       = (const float*)d_in[0];
    const float* W_left  = (const float*)d_in[1];
    const float* conv_w  = (const float*)d_in[2];
    const float* conv_b  = (const float*)d_in[3];
    const float* W_delta = (const float*)d_in[4];
    const float* b_delta = (const float*)d_in[5];
    const float* W_B     = (const float*)d_in[6];
    const float* W_C     = (const float*)d_in[7];
    const float* A_log   = (const float*)d_in[8];
    const float* W_right = (const float*)d_in[9];
    const float* ln_g    = (const float*)d_in[10];
    const float* ln_b    = (const float*)d_in[11];
    const float* W_out   = (const float*)d_in[12];
    float*       out     = (float*)d_out;

    float *left, *xl, *delta, *gate, *y, *BC;
    __half *x2, *wlr2, *wd3, *wo2, *xl3;
    cudaGetSymbolAddress((void**)&left,  g_left);
    cudaGetSymbolAddress((void**)&xl,    g_xl);
    cudaGetSymbolAddress((void**)&delta, g_delta);
    cudaGetSymbolAddress((void**)&gate,  g_gate);
    cudaGetSymbolAddress((void**)&y,     g_y);
    cudaGetSymbolAddress((void**)&BC,    g_BC);
    cudaGetSymbolAddress((void**)&x2,    g_x2);
    cudaGetSymbolAddress((void**)&wlr2,  g_wlr2);
    cudaGetSymbolAddress((void**)&wd3,   g_wd3);
    cudaGetSymbolAddress((void**)&wo2,   g_wo2);
    cudaGetSymbolAddress((void**)&xl3,   g_xl3);

    cudaFuncSetAttribute(hgemm_kernel<EPI_NONE>, cudaFuncAttributeMaxDynamicSharedMemorySize, HG_SMEM);
    cudaFuncSetAttribute(hgemm_kernel<EPI_DUAL>, cudaFuncAttributeMaxDynamicSharedMemorySize, HG_SMEM);
    cudaFuncSetAttribute(hgemm_kernel<EPI_RAW>,  cudaFuncAttributeMaxDynamicSharedMemorySize, HG_SMEM);

    size_t n4;

    // W_delta 3-term expansion
    n4 = (size_t)DI * DI / 4;
    expand3_kernel<1><<<(int)((n4 + 255) / 256), 256>>>(W_delta, wd3, DI, n4);

    // x 2-term expansion
    n4 = (size_t)MROWS * DM / 4;
    expand2_kernel<0><<<(int)((n4 + 255) / 256), 256>>>(x, x2, DM, n4);

    // merged [W_left; W_right] 2-term expansion
    n4 = (size_t)DI * DM / 4;
    expand2_dual_kernel<<<(int)((2 * n4 + 255) / 256), 256>>>(W_left, W_right, wlr2, DM, n4);

    // merged [left | gate] = x @ [W_left;W_right]^T  [8192 x 4096], K2=2048
    hgemm_kernel<EPI_DUAL><<<dim3(2 * DI / 128, MROWS / 128), 256, HG_SMEM>>>(
        x2, wlr2, nullptr, left, gate, MROWS, 2 * DI, 2 * DM);

    // xl = silu(causal_conv(left)) + fp16 3-term split into xl3
    // (after this, g_left is free -> reused as split-K partial 1)
    conv_silu_split_kernel<<<(int)(((size_t)MROWS * DI / 4 + 255) / 256), 256>>>(
        left, conv_w, conv_b, xl, xl3);

    // delta GEMM, K3=6144, 3-term, split-K=2 (partials: g_y, g_left)
    hgemm_kernel<EPI_RAW><<<dim3(DI / 128, MROWS / 128, 2), 256, HG_SMEM>>>(
        xl3, wd3, nullptr, y, left, MROWS, DI, 3 * DI);

    // deterministic reduction: delta = softplus_clip(p0 + p1 + bias)
    n4 = (size_t)MROWS * DI / 4;
    reduce_sp_kernel<<<(int)((n4 + 255) / 256), 256>>>(y, left, b_delta, delta, n4);

    // [Bm|Cm] = xl @ [W_B;W_C]^T  [8192 x 32], K=2048 (fp32 SIMT, pack fused)
    sgemm_bc_kernel<<<MROWS / 64, 256>>>(xl, W_B, W_C, BC, MROWS, DI);

    // selective scan (8 threads / channel, MLP=16 prefetch); writes g_y
    scan_kernel<<<(BB * DI * 8) / 256, 256>>>(delta, xl, BC, A_log, y);

    // LN(y*gate) -> fp16 2-term A planes (reuse xl3 buffer)
    ln_gate_split_kernel<<<MROWS, 256>>>(y, gate, ln_g, ln_b, xl3);

    // W_out 2-term expansion
    n4 = (size_t)DM * DI / 4;
    expand2_kernel<1><<<(int)((n4 + 255) / 256), 256>>>(W_out, wo2, DI, n4);

    // out = ln_out @ W_out^T  [8192 x 1024], K2=4096, 2-term
    hgemm_kernel<EPI_NONE><<<dim3(DM / 128, MROWS / 128), 256, HG_SMEM>>>(
        xl3, wo2, nullptr, out, nullptr, MROWS, DM, 2 * DI);
}